// round 1
// baseline (speedup 1.0000x reference)
#include <cuda_runtime.h>
#include <cstdint>

#define NTOK   131072
#define DIM    1024
#define NEXP   8
#define GBATCH 4
#define NBATCH (NTOK / GBATCH)   // 32768

// Swizzled Wt[d][e] in shared: byte offset (d*32 + e*4), swizzle = off ^ ((off>>3)&0x70)
__global__ __launch_bounds__(256)
void topk_gating_kernel(const float* __restrict__ x,
                        const float* __restrict__ W,
                        const float* __restrict__ b,
                        float* __restrict__ out)
{
    __shared__ float wt[NEXP * DIM];   // 32 KB

    const int tid = threadIdx.x;

    // ---- Stage W (row-major [E][D]) -> shared Wt[d][e], SW128-swizzled ----
    for (int i = tid; i < (NEXP * DIM) / 4; i += 256) {
        float4 v = reinterpret_cast<const float4*>(W)[i];
        int elem = i * 4;
        int e  = elem >> 10;       // expert
        int d0 = elem & 1023;      // starting d
        float vv[4] = {v.x, v.y, v.z, v.w};
        #pragma unroll
        for (int j = 0; j < 4; j++) {
            int off = (d0 + j) * 32 + e * 4;            // byte offset in Wt
            int s   = off ^ ((off >> 3) & 0x70);        // SW128 swizzle
            wt[s >> 2] = vv[j];
        }
    }
    __syncthreads();

    const int lane  = tid & 31;
    const int warp  = tid >> 5;
    const int gwarp = blockIdx.x * 8 + warp;
    const int nwarps = gridDim.x * 8;
    const unsigned FULL = 0xffffffffu;

    const float bias = __ldg(&b[lane & 7]);   // this lane's expert bias (fixed)

    // Per-lane swizzled base for its 4 Wt rows: off = i*4096 + lane*128 + ((j*32+c*16) ^ xr)
    const int xr = (lane & 7) * 16;
    const char* wbase = reinterpret_cast<const char*>(wt) + lane * 128;

    for (int batch = gwarp; batch < NBATCH; batch += nwarps) {
        const int t0 = batch * GBATCH;
        const float* xp = x + (size_t)t0 * DIM + lane * 4;

        float acc[GBATCH][NEXP];
        #pragma unroll
        for (int g = 0; g < GBATCH; g++)
            #pragma unroll
            for (int e = 0; e < NEXP; e++) acc[g][e] = 0.f;

        #pragma unroll
        for (int i = 0; i < 8; i++) {
            // 8 LDS.128: Wt rows d = i*128 + lane*4 + j, experts [4c..4c+3]
            float4 w4[8];
            #pragma unroll
            for (int j = 0; j < 4; j++)
                #pragma unroll
                for (int c = 0; c < 2; c++)
                    w4[j * 2 + c] = *reinterpret_cast<const float4*>(
                        wbase + i * 4096 + ((j * 32 + c * 16) ^ xr));

            #pragma unroll
            for (int g = 0; g < GBATCH; g++) {
                float4 xv = *reinterpret_cast<const float4*>(xp + g * DIM + i * 128);
                float xs[4] = {xv.x, xv.y, xv.z, xv.w};
                #pragma unroll
                for (int j = 0; j < 4; j++) {
                    float4 wa = w4[j * 2];
                    float4 wb = w4[j * 2 + 1];
                    acc[g][0] += xs[j] * wa.x;
                    acc[g][1] += xs[j] * wa.y;
                    acc[g][2] += xs[j] * wa.z;
                    acc[g][3] += xs[j] * wa.w;
                    acc[g][4] += xs[j] * wb.x;
                    acc[g][5] += xs[j] * wb.y;
                    acc[g][6] += xs[j] * wb.z;
                    acc[g][7] += xs[j] * wb.w;
                }
            }
        }

        // ---- per-token reduce + softmax + top2 ----
        #pragma unroll
        for (int g = 0; g < GBATCH; g++) {
            float q[8];
            #pragma unroll
            for (int e = 0; e < NEXP; e++) q[e] = acc[g][e];

            // segmented butterfly: lane bit k fixes expert bit k, reduces over that bit
            { // bit 2 (xor 4): 8 -> 4 live
                bool hi = (lane & 4) != 0;
                #pragma unroll
                for (int j = 0; j < 4; j++) {
                    float send = hi ? q[j] : q[j + 4];
                    float recv = __shfl_xor_sync(FULL, send, 4);
                    q[j] = (hi ? q[j + 4] : q[j]) + recv;
                }
            }
            { // bit 1 (xor 2): 4 -> 2 live
                bool hi = (lane & 2) != 0;
                #pragma unroll
                for (int j = 0; j < 2; j++) {
                    float send = hi ? q[j] : q[j + 2];
                    float recv = __shfl_xor_sync(FULL, send, 2);
                    q[j] = (hi ? q[j + 2] : q[j]) + recv;
                }
            }
            float v;
            { // bit 0 (xor 1): 2 -> 1 live
                bool hi = (lane & 1) != 0;
                float send = hi ? q[0] : q[1];
                float recv = __shfl_xor_sync(FULL, send, 1);
                v = (hi ? q[1] : q[0]) + recv;
            }
            // reduce across octets; every lane ends with logit[lane&7]
            v += __shfl_xor_sync(FULL, v, 8);
            v += __shfl_xor_sync(FULL, v, 16);
            v += bias;

            // softmax over the 8 logits (replicated per octet)
            float m = v;
            m = fmaxf(m, __shfl_xor_sync(FULL, m, 1));
            m = fmaxf(m, __shfl_xor_sync(FULL, m, 2));
            m = fmaxf(m, __shfl_xor_sync(FULL, m, 4));
            float ex = __expf(v - m);
            float s = ex;
            s += __shfl_xor_sync(FULL, s, 1);
            s += __shfl_xor_sync(FULL, s, 2);
            s += __shfl_xor_sync(FULL, s, 4);
            float prob = ex / s;

            // top-2 via monotone key (prob > 0 => positive float bits are order-preserving)
            unsigned key = (__float_as_uint(prob) & ~7u) | (unsigned)(lane & 7);
            unsigned k1 = key, r;
            r = __shfl_xor_sync(FULL, k1, 1); k1 = r > k1 ? r : k1;
            r = __shfl_xor_sync(FULL, k1, 2); k1 = r > k1 ? r : k1;
            r = __shfl_xor_sync(FULL, k1, 4); k1 = r > k1 ? r : k1;
            unsigned k2 = (key == k1) ? 0u : key;
            r = __shfl_xor_sync(FULL, k2, 1); k2 = r > k2 ? r : k2;
            r = __shfl_xor_sync(FULL, k2, 2); k2 = r > k2 ? r : k2;
            r = __shfl_xor_sync(FULL, k2, 4); k2 = r > k2 ? r : k2;

            int i0 = (int)(k1 & 7u);
            int i1 = (int)(k2 & 7u);
            float v0 = __shfl_sync(FULL, prob, i0);   // exact prob of winner
            float v1 = __shfl_sync(FULL, prob, i1);

            if (lane == 0) {
                int t = t0 + g;
                *reinterpret_cast<float2*>(out + 2 * t) =
                    make_float2((float)i0, (float)i1);
                *reinterpret_cast<float2*>(out + 2 * NTOK + 2 * t) =
                    make_float2(v0, v1);
            }
        }
    }
}

extern "C" void kernel_launch(void* const* d_in, const int* in_sizes, int n_in,
                              void* d_out, int out_size)
{
    const float* x = (const float*)d_in[0];
    const float* W = (const float*)d_in[1];
    const float* b = (const float*)d_in[2];
    float* out = (float*)d_out;
    (void)in_sizes; (void)n_in; (void)out_size;

    // 2048 blocks x 8 warps = 16384 warps; 32768 batches -> 2 per warp
    topk_gating_kernel<<<2048, 256>>>(x, W, b, out);
}

// round 2
// speedup vs baseline: 2.1767x; 2.1767x over previous
#include <cuda_runtime.h>
#include <cstdint>

#define NTOK   131072
#define DIM    1024
#define NEXP   8
#define GBATCH 4
#define NBATCH (NTOK / GBATCH)   // 32768

__device__ __forceinline__ uint64_t pack2(float lo, float hi) {
    uint64_t r;
    asm("mov.b64 %0, {%1, %2};" : "=l"(r) : "f"(lo), "f"(hi));
    return r;
}
__device__ __forceinline__ void unpack2(uint64_t v, float& lo, float& hi) {
    asm("mov.b64 {%0, %1}, %2;" : "=f"(lo), "=f"(hi) : "l"(v));
}
// Packed dual-FMA: acc.lo += a.lo*b.lo; acc.hi += a.hi*b.hi  (single FFMA2 on sm_103a)
__device__ __forceinline__ void ffma2(uint64_t& acc, uint64_t a, uint64_t b) {
    asm("fma.rn.f32x2 %0, %1, %2, %0;" : "+l"(acc) : "l"(a), "l"(b));
}

// Swizzled Wt[d][e] in shared: byte offset (d*32 + e*4), swizzle = off ^ ((off>>3)&0x70)
__global__ __launch_bounds__(256, 2)
void topk_gating_kernel(const float* __restrict__ x,
                        const float* __restrict__ W,
                        const float* __restrict__ b,
                        float* __restrict__ out)
{
    __shared__ float wt[NEXP * DIM];   // 32 KB

    const int tid = threadIdx.x;

    // ---- Stage W (row-major [E][D]) -> shared Wt[d][e], SW128-swizzled ----
    for (int i = tid; i < (NEXP * DIM) / 4; i += 256) {
        float4 v = reinterpret_cast<const float4*>(W)[i];
        int elem = i * 4;
        int e  = elem >> 10;       // expert
        int d0 = elem & 1023;      // starting d
        float vv[4] = {v.x, v.y, v.z, v.w};
        #pragma unroll
        for (int j = 0; j < 4; j++) {
            int off = (d0 + j) * 32 + e * 4;            // byte offset in Wt
            int s   = off ^ ((off >> 3) & 0x70);        // SW128 swizzle
            wt[s >> 2] = vv[j];
        }
    }
    __syncthreads();

    const int lane  = tid & 31;
    const int warp  = tid >> 5;
    const int gwarp = blockIdx.x * 8 + warp;
    const int nwarps = gridDim.x * 8;
    const unsigned FULL = 0xffffffffu;

    const float bias = __ldg(&b[lane & 7]);   // this lane's expert bias (fixed)

    // Per-lane swizzled smem offsets for its 4 Wt rows (8 LDS.128 per 128-d chunk):
    // base byte offset = lane*128 + ((j*32 + c*16) ^ ((lane&7)*16)), j=0..3, c=0..1
    const int xr = (lane & 7) * 16;
    int soff[8];
    #pragma unroll
    for (int j = 0; j < 4; j++)
        #pragma unroll
        for (int c = 0; c < 2; c++)
            soff[j * 2 + c] = lane * 128 + ((j * 32 + c * 16) ^ xr);
    const char* wtb = reinterpret_cast<const char*>(wt);

    for (int batch = gwarp; batch < NBATCH; batch += nwarps) {
        const int t0 = batch * GBATCH;
        const float* xp = x + (size_t)t0 * DIM + lane * 4;

        // Packed accumulators: acc[g][p] holds experts (2p, 2p+1)
        uint64_t acc[GBATCH][4];
        #pragma unroll
        for (int g = 0; g < GBATCH; g++)
            #pragma unroll
            for (int p = 0; p < 4; p++) acc[g][p] = 0ULL;

        #pragma unroll 1
        for (int i = 0; i < 8; i++) {
            // front-issue 4 independent LDG.128 (x for 4 tokens)
            float4 xv[GBATCH];
            #pragma unroll
            for (int g = 0; g < GBATCH; g++)
                xv[g] = *reinterpret_cast<const float4*>(xp + g * DIM + i * 128);

            // 8 LDS.128 -> W pairs. wq[j][0]={e0e1,e2e3}, wq[j][1]={e4e5,e6e7}
            ulonglong2 wq[4][2];
            #pragma unroll
            for (int j = 0; j < 4; j++)
                #pragma unroll
                for (int c = 0; c < 2; c++)
                    wq[j][c] = *reinterpret_cast<const ulonglong2*>(
                        wtb + i * 4096 + soff[j * 2 + c]);

            #pragma unroll
            for (int g = 0; g < GBATCH; g++) {
                float xs[4] = {xv[g].x, xv[g].y, xv[g].z, xv[g].w};
                #pragma unroll
                for (int j = 0; j < 4; j++) {
                    uint64_t xpp = pack2(xs[j], xs[j]);
                    ffma2(acc[g][0], xpp, wq[j][0].x);
                    ffma2(acc[g][1], xpp, wq[j][0].y);
                    ffma2(acc[g][2], xpp, wq[j][1].x);
                    ffma2(acc[g][3], xpp, wq[j][1].y);
                }
            }
        }

        // ---- per-token reduce + softmax + top2 ----
        #pragma unroll
        for (int g = 0; g < GBATCH; g++) {
            float q[8];
            #pragma unroll
            for (int p = 0; p < 4; p++) unpack2(acc[g][p], q[2 * p], q[2 * p + 1]);

            // segmented butterfly: lane bit k fixes expert bit k, reduces over that bit
            { // bit 2 (xor 4): 8 -> 4 live
                bool hi = (lane & 4) != 0;
                #pragma unroll
                for (int j = 0; j < 4; j++) {
                    float send = hi ? q[j] : q[j + 4];
                    float recv = __shfl_xor_sync(FULL, send, 4);
                    q[j] = (hi ? q[j + 4] : q[j]) + recv;
                }
            }
            { // bit 1 (xor 2): 4 -> 2 live
                bool hi = (lane & 2) != 0;
                #pragma unroll
                for (int j = 0; j < 2; j++) {
                    float send = hi ? q[j] : q[j + 2];
                    float recv = __shfl_xor_sync(FULL, send, 2);
                    q[j] = (hi ? q[j + 2] : q[j]) + recv;
                }
            }
            float v;
            { // bit 0 (xor 1): 2 -> 1 live
                bool hi = (lane & 1) != 0;
                float send = hi ? q[0] : q[1];
                float recv = __shfl_xor_sync(FULL, send, 1);
                v = (hi ? q[1] : q[0]) + recv;
            }
            // reduce across octets; every lane ends with logit[lane&7]
            v += __shfl_xor_sync(FULL, v, 8);
            v += __shfl_xor_sync(FULL, v, 16);
            v += bias;

            // softmax over the 8 logits (replicated per octet)
            float m = v;
            m = fmaxf(m, __shfl_xor_sync(FULL, m, 1));
            m = fmaxf(m, __shfl_xor_sync(FULL, m, 2));
            m = fmaxf(m, __shfl_xor_sync(FULL, m, 4));
            float ex = __expf(v - m);
            float s = ex;
            s += __shfl_xor_sync(FULL, s, 1);
            s += __shfl_xor_sync(FULL, s, 2);
            s += __shfl_xor_sync(FULL, s, 4);
            float prob = ex / s;

            // top-2 via monotone key (prob > 0 => positive float bits are order-preserving)
            unsigned key = (__float_as_uint(prob) & ~7u) | (unsigned)(lane & 7);
            unsigned k1 = key, r;
            r = __shfl_xor_sync(FULL, k1, 1); k1 = r > k1 ? r : k1;
            r = __shfl_xor_sync(FULL, k1, 2); k1 = r > k1 ? r : k1;
            r = __shfl_xor_sync(FULL, k1, 4); k1 = r > k1 ? r : k1;
            unsigned k2 = (key == k1) ? 0u : key;
            r = __shfl_xor_sync(FULL, k2, 1); k2 = r > k2 ? r : k2;
            r = __shfl_xor_sync(FULL, k2, 2); k2 = r > k2 ? r : k2;
            r = __shfl_xor_sync(FULL, k2, 4); k2 = r > k2 ? r : k2;

            int i0 = (int)(k1 & 7u);
            int i1 = (int)(k2 & 7u);
            float v0 = __shfl_sync(FULL, prob, i0);   // exact prob of winner
            float v1 = __shfl_sync(FULL, prob, i1);

            if (lane == 0) {
                int t = t0 + g;
                *reinterpret_cast<float2*>(out + 2 * t) =
                    make_float2((float)i0, (float)i1);
                *reinterpret_cast<float2*>(out + 2 * NTOK + 2 * t) =
                    make_float2(v0, v1);
            }
        }
    }
}

extern "C" void kernel_launch(void* const* d_in, const int* in_sizes, int n_in,
                              void* d_out, int out_size)
{
    const float* x = (const float*)d_in[0];
    const float* W = (const float*)d_in[1];
    const float* b = (const float*)d_in[2];
    float* out = (float*)d_out;
    (void)in_sizes; (void)n_in; (void)out_size;

    // 2048 blocks x 8 warps = 16384 warps; 32768 batches -> 2 per warp
    topk_gating_kernel<<<2048, 256>>>(x, W, b, out);
}

// round 3
// speedup vs baseline: 2.2445x; 1.0311x over previous
#include <cuda_runtime.h>
#include <cstdint>

#define NTOK   131072
#define DIM    1024
#define NEXP   8
#define GBATCH 4
#define NBATCH (NTOK / GBATCH)   // 32768

__device__ __forceinline__ uint64_t pack2(float lo, float hi) {
    uint64_t r;
    asm("mov.b64 %0, {%1, %2};" : "=l"(r) : "f"(lo), "f"(hi));
    return r;
}
__device__ __forceinline__ void unpack2(uint64_t v, float& lo, float& hi) {
    asm("mov.b64 {%0, %1}, %2;" : "=f"(lo), "=f"(hi) : "l"(v));
}
// Packed dual-FMA: acc.lo += a.lo*b.lo; acc.hi += a.hi*b.hi  (single FFMA2 on sm_103a)
__device__ __forceinline__ void ffma2(uint64_t& acc, uint64_t a, uint64_t b) {
    asm("fma.rn.f32x2 %0, %1, %2, %0;" : "+l"(acc) : "l"(a), "l"(b));
}

// Swizzled Wt[d][e] in shared: byte offset (d*32 + e*4), swizzle = off ^ ((off>>3)&0x70)
__global__ __launch_bounds__(256, 2)
void topk_gating_kernel(const float* __restrict__ x,
                        const float* __restrict__ W,
                        const float* __restrict__ b,
                        float* __restrict__ out)
{
    __shared__ float wt[NEXP * DIM];   // 32 KB

    const int tid = threadIdx.x;

    // ---- Stage W (row-major [E][D]) -> shared Wt[d][e], SW128-swizzled ----
    for (int i = tid; i < (NEXP * DIM) / 4; i += 256) {
        float4 v = reinterpret_cast<const float4*>(W)[i];
        int elem = i * 4;
        int e  = elem >> 10;       // expert
        int d0 = elem & 1023;      // starting d
        float vv[4] = {v.x, v.y, v.z, v.w};
        #pragma unroll
        for (int j = 0; j < 4; j++) {
            int off = (d0 + j) * 32 + e * 4;            // byte offset in Wt
            int s   = off ^ ((off >> 3) & 0x70);        // SW128 swizzle
            wt[s >> 2] = vv[j];
        }
    }
    __syncthreads();

    const int lane  = tid & 31;
    const int warp  = tid >> 5;
    const int gwarp = blockIdx.x * 8 + warp;
    const int nwarps = gridDim.x * 8;
    const unsigned FULL = 0xffffffffu;

    const float bias = __ldg(&b[lane & 7]);   // this lane's expert bias (fixed)

    // Per-lane swizzled smem offsets for its 4 Wt rows (8 LDS.128 per 128-d chunk)
    const int xr = (lane & 7) * 16;
    int soff[8];
    #pragma unroll
    for (int j = 0; j < 4; j++)
        #pragma unroll
        for (int c = 0; c < 2; c++)
            soff[j * 2 + c] = lane * 128 + ((j * 32 + c * 16) ^ xr);
    const char* wtb = reinterpret_cast<const char*>(wt);

    int batch = gwarp;
    if (batch >= NBATCH) return;
    const float* xp = x + (size_t)batch * GBATCH * DIM + lane * 4;

    // Prime the pipeline: x chunk 0 of first batch
    float4 xv[GBATCH];
    #pragma unroll
    for (int g = 0; g < GBATCH; g++)
        xv[g] = *reinterpret_cast<const float4*>(xp + g * DIM);

    while (true) {
        const int nbatch = batch + nwarps;
        const bool has_next = (nbatch < NBATCH);
        const float* xpn = has_next
            ? x + (size_t)nbatch * GBATCH * DIM + lane * 4
            : xp;   // harmless re-read on final batch

        // Packed accumulators: acc[g][p] holds experts (2p, 2p+1)
        uint64_t acc[GBATCH][4];
        #pragma unroll
        for (int g = 0; g < GBATCH; g++)
            #pragma unroll
            for (int p = 0; p < 4; p++) acc[g][p] = 0ULL;

        #pragma unroll 1
        for (int i = 0; i < 8; i++) {
            // 1) prefetch next chunk's x (crosses into next batch at i==7)
            const float* pf = (i < 7) ? (xp + (i + 1) * 128) : xpn;
            float4 xn[GBATCH];
            #pragma unroll
            for (int g = 0; g < GBATCH; g++)
                xn[g] = *reinterpret_cast<const float4*>(pf + g * DIM);

            // 2) W pairs for this chunk: 8 LDS.128
            ulonglong2 wq[4][2];
            #pragma unroll
            for (int j = 0; j < 4; j++)
                #pragma unroll
                for (int c = 0; c < 2; c++)
                    wq[j][c] = *reinterpret_cast<const ulonglong2*>(
                        wtb + i * 4096 + soff[j * 2 + c]);

            // 3) FFMA2 on previously-fetched x
            #pragma unroll
            for (int g = 0; g < GBATCH; g++) {
                float xs[4] = {xv[g].x, xv[g].y, xv[g].z, xv[g].w};
                #pragma unroll
                for (int j = 0; j < 4; j++) {
                    uint64_t xpp = pack2(xs[j], xs[j]);
                    ffma2(acc[g][0], xpp, wq[j][0].x);
                    ffma2(acc[g][1], xpp, wq[j][0].y);
                    ffma2(acc[g][2], xpp, wq[j][1].x);
                    ffma2(acc[g][3], xpp, wq[j][1].y);
                }
            }

            #pragma unroll
            for (int g = 0; g < GBATCH; g++) xv[g] = xn[g];
        }

        // ---- per-token reduce + softmax + top2 ----
        const int t0 = batch * GBATCH;
        #pragma unroll
        for (int g = 0; g < GBATCH; g++) {
            float q[8];
            #pragma unroll
            for (int p = 0; p < 4; p++) unpack2(acc[g][p], q[2 * p], q[2 * p + 1]);

            { // lane bit 2 fixes expert bit 2
                bool hi = (lane & 4) != 0;
                #pragma unroll
                for (int j = 0; j < 4; j++) {
                    float send = hi ? q[j] : q[j + 4];
                    float recv = __shfl_xor_sync(FULL, send, 4);
                    q[j] = (hi ? q[j + 4] : q[j]) + recv;
                }
            }
            { // lane bit 1
                bool hi = (lane & 2) != 0;
                #pragma unroll
                for (int j = 0; j < 2; j++) {
                    float send = hi ? q[j] : q[j + 2];
                    float recv = __shfl_xor_sync(FULL, send, 2);
                    q[j] = (hi ? q[j + 2] : q[j]) + recv;
                }
            }
            float v;
            { // lane bit 0
                bool hi = (lane & 1) != 0;
                float send = hi ? q[0] : q[1];
                float recv = __shfl_xor_sync(FULL, send, 1);
                v = (hi ? q[1] : q[0]) + recv;
            }
            v += __shfl_xor_sync(FULL, v, 8);
            v += __shfl_xor_sync(FULL, v, 16);
            v += bias;

            // softmax over 8 logits (replicated per octet)
            float m = v;
            m = fmaxf(m, __shfl_xor_sync(FULL, m, 1));
            m = fmaxf(m, __shfl_xor_sync(FULL, m, 2));
            m = fmaxf(m, __shfl_xor_sync(FULL, m, 4));
            float ex = __expf(v - m);
            float s = ex;
            s += __shfl_xor_sync(FULL, s, 1);
            s += __shfl_xor_sync(FULL, s, 2);
            s += __shfl_xor_sync(FULL, s, 4);
            float prob = ex / s;

            // top-2 via monotone key
            unsigned key = (__float_as_uint(prob) & ~7u) | (unsigned)(lane & 7);
            unsigned k1 = key, r;
            r = __shfl_xor_sync(FULL, k1, 1); k1 = r > k1 ? r : k1;
            r = __shfl_xor_sync(FULL, k1, 2); k1 = r > k1 ? r : k1;
            r = __shfl_xor_sync(FULL, k1, 4); k1 = r > k1 ? r : k1;
            unsigned k2 = (key == k1) ? 0u : key;
            r = __shfl_xor_sync(FULL, k2, 1); k2 = r > k2 ? r : k2;
            r = __shfl_xor_sync(FULL, k2, 2); k2 = r > k2 ? r : k2;
            r = __shfl_xor_sync(FULL, k2, 4); k2 = r > k2 ? r : k2;

            int i0 = (int)(k1 & 7u);
            int i1 = (int)(k2 & 7u);
            float v0 = __shfl_sync(FULL, prob, i0);
            float v1 = __shfl_sync(FULL, prob, i1);

            if (lane == 0) {
                int t = t0 + g;
                *reinterpret_cast<float2*>(out + 2 * t) =
                    make_float2((float)i0, (float)i1);
                *reinterpret_cast<float2*>(out + 2 * NTOK + 2 * t) =
                    make_float2(v0, v1);
            }
        }

        if (!has_next) break;
        batch = nbatch;
        xp = xpn;
    }
}

extern "C" void kernel_launch(void* const* d_in, const int* in_sizes, int n_in,
                              void* d_out, int out_size)
{
    const float* x = (const float*)d_in[0];
    const float* W = (const float*)d_in[1];
    const float* b = (const float*)d_in[2];
    float* out = (float*)d_out;
    (void)in_sizes; (void)n_in; (void)out_size;

    // 2048 blocks x 8 warps = 16384 warps; 32768 batches -> 2 per warp
    topk_gating_kernel<<<2048, 256>>>(x, W, b, out);
}

// round 5
// speedup vs baseline: 2.7606x; 1.2300x over previous
#include <cuda_runtime.h>
#include <cstdint>

#define NTOK   131072
#define DIM    1024
#define NEXP   8
#define GBATCH 4
#define NBATCH (NTOK / GBATCH)   // 32768
#define DEPTH  4                 // x staging ring depth (chunks)
#define CHUNK_FLOATS (GBATCH * 128)          // 512 floats = 2KB per stage
#define WT_FLOATS    (NEXP * DIM)            // 8192 floats = 32KB
#define SMEM_FLOATS  (WT_FLOATS + 8 * DEPTH * CHUNK_FLOATS)   // 96KB total
#define SMEM_BYTES   (SMEM_FLOATS * 4)

__device__ __forceinline__ uint64_t pack2(float lo, float hi) {
    uint64_t r;
    asm("mov.b64 %0, {%1, %2};" : "=l"(r) : "f"(lo), "f"(hi));
    return r;
}
__device__ __forceinline__ void unpack2(uint64_t v, float& lo, float& hi) {
    asm("mov.b64 {%0, %1}, %2;" : "=f"(lo), "=f"(hi) : "l"(v));
}
// Packed dual-FMA: acc.lo += a.lo*b.lo; acc.hi += a.hi*b.hi  (single FFMA2 on sm_103a)
__device__ __forceinline__ void ffma2(uint64_t& acc, uint64_t a, uint64_t b) {
    asm("fma.rn.f32x2 %0, %1, %2, %0;" : "+l"(acc) : "l"(a), "l"(b));
}
__device__ __forceinline__ void cp_async16(uint32_t saddr, const float* gptr) {
    asm volatile("cp.async.cg.shared.global [%0], [%1], 16;"
                 :: "r"(saddr), "l"(gptr));
}
#define CP_COMMIT() asm volatile("cp.async.commit_group;" ::: "memory")
#define CP_WAIT3()  asm volatile("cp.async.wait_group 3;" ::: "memory")

__global__ __launch_bounds__(256, 2)
void topk_gating_kernel(const float* __restrict__ x,
                        const float* __restrict__ W,
                        const float* __restrict__ b,
                        float* __restrict__ out)
{
    extern __shared__ __align__(128) float smem[];
    float* wt = smem;                       // Wt[d][e], SW128-swizzled, 32KB

    const int tid  = threadIdx.x;
    const int lane = tid & 31;
    const int warp = tid >> 5;

    // ---- Stage W (row-major [E][D]) -> shared Wt[d][e], SW128-swizzled ----
    for (int i = tid; i < WT_FLOATS / 4; i += 256) {
        float4 v = reinterpret_cast<const float4*>(W)[i];
        int elem = i * 4;
        int e  = elem >> 10;       // expert
        int d0 = elem & 1023;      // starting d
        float vv[4] = {v.x, v.y, v.z, v.w};
        #pragma unroll
        for (int j = 0; j < 4; j++) {
            int off = (d0 + j) * 32 + e * 4;            // byte offset in Wt
            int s   = off ^ ((off >> 3) & 0x70);        // SW128 swizzle
            wt[s >> 2] = vv[j];
        }
    }
    __syncthreads();

    const int gwarp  = blockIdx.x * 8 + warp;
    const int nwarps = gridDim.x * 8;
    const unsigned FULL = 0xffffffffu;

    const float bias = __ldg(&b[lane & 7]);

    // Per-lane swizzled smem offsets for its 4 Wt rows (8 LDS.128 per 128-d chunk)
    const int xr = (lane & 7) * 16;
    int soff[8];
    #pragma unroll
    for (int j = 0; j < 4; j++)
        #pragma unroll
        for (int c = 0; c < 2; c++)
            soff[j * 2 + c] = lane * 128 + ((j * 32 + c * 16) ^ xr);
    const char* wtb = reinterpret_cast<const char*>(wt);

    // Per-warp x staging ring: DEPTH stages x 2KB
    const int lo4 = lane * 4;   // this lane's float offset within a token row chunk
    float* xring = smem + WT_FLOATS + warp * (DEPTH * CHUNK_FLOATS);
    // per-LANE smem base for cp.async destinations (BUGFIX: include lane*16)
    uint32_t xring_s = (uint32_t)__cvta_generic_to_shared(xring) + (uint32_t)lo4 * 4u;

    int batch = gwarp;
    if (batch >= NBATCH) return;
    const float* xp = x + (size_t)batch * GBATCH * DIM + lo4;

    // ---- Prime: issue chunks 0,1,2 of first batch into stages 0,1,2 ----
    #pragma unroll
    for (int k = 0; k < DEPTH - 1; k++) {
        uint32_t sdst = xring_s + (uint32_t)(k * CHUNK_FLOATS) * 4u;
        #pragma unroll
        for (int g = 0; g < GBATCH; g++)
            cp_async16(sdst + g * 512u, xp + g * DIM + k * 128);
        CP_COMMIT();
    }

    while (true) {
        const int nbatch = batch + nwarps;
        const bool has_next = (nbatch < NBATCH);
        const float* xpn = x + (size_t)nbatch * GBATCH * DIM + lo4;

        uint64_t acc[GBATCH][4];
        #pragma unroll
        for (int g = 0; g < GBATCH; g++)
            #pragma unroll
            for (int p = 0; p < 4; p++) acc[g][p] = 0ULL;

        #pragma unroll 1
        for (int i = 0; i < 8; i++) {
            // 1) issue chunk i+3 (crosses into next batch for i >= 5)
            if (i < 5) {
                uint32_t sdst = xring_s + (uint32_t)(((i + 3) & 3) * CHUNK_FLOATS) * 4u;
                const float* src = xp + (i + 3) * 128;
                #pragma unroll
                for (int g = 0; g < GBATCH; g++)
                    cp_async16(sdst + g * 512u, src + g * DIM);
            } else if (has_next) {
                uint32_t sdst = xring_s + (uint32_t)(((i + 3) & 3) * CHUNK_FLOATS) * 4u;
                const float* src = xpn + (i - 5) * 128;
                #pragma unroll
                for (int g = 0; g < GBATCH; g++)
                    cp_async16(sdst + g * 512u, src + g * DIM);
            }
            CP_COMMIT();          // one group per iteration, even if empty
            CP_WAIT3();           // chunk i is now resident

            // 2) W pairs for this chunk: 8 LDS.128
            ulonglong2 wq[4][2];
            #pragma unroll
            for (int j = 0; j < 4; j++)
                #pragma unroll
                for (int c = 0; c < 2; c++)
                    wq[j][c] = *reinterpret_cast<const ulonglong2*>(
                        wtb + i * 4096 + soff[j * 2 + c]);

            // 3) consume x chunk i from its ring stage + FFMA2
            const float* xs_base = xring + (i & 3) * CHUNK_FLOATS + lo4;
            #pragma unroll
            for (int g = 0; g < GBATCH; g++) {
                float4 xv = *reinterpret_cast<const float4*>(xs_base + g * 128);
                float xsv[4] = {xv.x, xv.y, xv.z, xv.w};
                #pragma unroll
                for (int j = 0; j < 4; j++) {
                    uint64_t xpp = pack2(xsv[j], xsv[j]);
                    ffma2(acc[g][0], xpp, wq[j][0].x);
                    ffma2(acc[g][1], xpp, wq[j][0].y);
                    ffma2(acc[g][2], xpp, wq[j][1].x);
                    ffma2(acc[g][3], xpp, wq[j][1].y);
                }
            }
        }

        // ---- per-token reduce + softmax + top2 ----
        const int t0 = batch * GBATCH;
        #pragma unroll
        for (int g = 0; g < GBATCH; g++) {
            float q[8];
            #pragma unroll
            for (int p = 0; p < 4; p++) unpack2(acc[g][p], q[2 * p], q[2 * p + 1]);

            { // lane bit 2 fixes expert bit 2
                bool hi = (lane & 4) != 0;
                #pragma unroll
                for (int j = 0; j < 4; j++) {
                    float send = hi ? q[j] : q[j + 4];
                    float recv = __shfl_xor_sync(FULL, send, 4);
                    q[j] = (hi ? q[j + 4] : q[j]) + recv;
                }
            }
            { // lane bit 1
                bool hi = (lane & 2) != 0;
                #pragma unroll
                for (int j = 0; j < 2; j++) {
                    float send = hi ? q[j] : q[j + 2];
                    float recv = __shfl_xor_sync(FULL, send, 2);
                    q[j] = (hi ? q[j + 2] : q[j]) + recv;
                }
            }
            float v;
            { // lane bit 0
                bool hi = (lane & 1) != 0;
                float send = hi ? q[0] : q[1];
                float recv = __shfl_xor_sync(FULL, send, 1);
                v = (hi ? q[1] : q[0]) + recv;
            }
            v += __shfl_xor_sync(FULL, v, 8);
            v += __shfl_xor_sync(FULL, v, 16);
            v += bias;

            // softmax over 8 logits (replicated per octet)
            float m = v;
            m = fmaxf(m, __shfl_xor_sync(FULL, m, 1));
            m = fmaxf(m, __shfl_xor_sync(FULL, m, 2));
            m = fmaxf(m, __shfl_xor_sync(FULL, m, 4));
            float ex = __expf(v - m);
            float s = ex;
            s += __shfl_xor_sync(FULL, s, 1);
            s += __shfl_xor_sync(FULL, s, 2);
            s += __shfl_xor_sync(FULL, s, 4);
            float prob = ex / s;

            // top-2 via monotone key
            unsigned key = (__float_as_uint(prob) & ~7u) | (unsigned)(lane & 7);
            unsigned k1 = key, r;
            r = __shfl_xor_sync(FULL, k1, 1); k1 = r > k1 ? r : k1;
            r = __shfl_xor_sync(FULL, k1, 2); k1 = r > k1 ? r : k1;
            r = __shfl_xor_sync(FULL, k1, 4); k1 = r > k1 ? r : k1;
            unsigned k2 = (key == k1) ? 0u : key;
            r = __shfl_xor_sync(FULL, k2, 1); k2 = r > k2 ? r : k2;
            r = __shfl_xor_sync(FULL, k2, 2); k2 = r > k2 ? r : k2;
            r = __shfl_xor_sync(FULL, k2, 4); k2 = r > k2 ? r : k2;

            int i0 = (int)(k1 & 7u);
            int i1 = (int)(k2 & 7u);
            float v0 = __shfl_sync(FULL, prob, i0);
            float v1 = __shfl_sync(FULL, prob, i1);

            if (lane == 0) {
                int t = t0 + g;
                *reinterpret_cast<float2*>(out + 2 * t) =
                    make_float2((float)i0, (float)i1);
                *reinterpret_cast<float2*>(out + 2 * NTOK + 2 * t) =
                    make_float2(v0, v1);
            }
        }

        if (!has_next) break;
        batch = nbatch;
        xp = xpn;
    }
}

extern "C" void kernel_launch(void* const* d_in, const int* in_sizes, int n_in,
                              void* d_out, int out_size)
{
    const float* x = (const float*)d_in[0];
    const float* W = (const float*)d_in[1];
    const float* b = (const float*)d_in[2];
    float* out = (float*)d_out;
    (void)in_sizes; (void)n_in; (void)out_size;

    cudaFuncSetAttribute(topk_gating_kernel,
                         cudaFuncAttributeMaxDynamicSharedMemorySize, SMEM_BYTES);

    // 2048 blocks x 8 warps = 16384 warps; 32768 batches -> 2 per warp
    topk_gating_kernel<<<2048, 256, SMEM_BYTES>>>(x, W, b, out);
}